// round 2
// baseline (speedup 1.0000x reference)
#include <cuda_runtime.h>
#include <math.h>

#define DH 128
#define NMAX 50016
#define EMAX 800000

// ---------------- scratch (device globals; no allocation allowed) ----------------
__device__ float g_dinv[NMAX];
__device__ float g_h1[(size_t)NMAX * DH];   // transformed features (pre-aggregation, pre-scaled by dinv)
__device__ float g_h2[(size_t)NMAX * DH];   // aggregated features
__device__ float g_sum[DH];
__device__ float g_sq[DH];
__device__ float g_bna[DH];                 // a = gamma * rstd
__device__ float g_bnb[DH];                 // b = beta - mu * a

// ---------------- degree / normalization ----------------
__global__ void k_deg_init(float* deg, int n) {
    int i = blockIdx.x * blockDim.x + threadIdx.x;
    if (i < n) deg[i] = 1.0f;               // self-loop
}

__global__ void k_deg_acc(const int* __restrict__ dst, float* deg, int E) {
    int e = blockIdx.x * blockDim.x + threadIdx.x;
    if (e < E) atomicAdd(&deg[dst[e]], 1.0f);
}

__global__ void k_rsqrt(float* deg, int n) {
    int i = blockIdx.x * blockDim.x + threadIdx.x;
    if (i < n) deg[i] = rsqrtf(deg[i]);
}

// ---------------- SGEMM: C[n,128] = A[n,128] @ W[128,128] ----------------
// BM=64 rows/block, BK=16, 256 threads, each thread computes 4x8
__global__ __launch_bounds__(256) void gemm128(
    const float* __restrict__ A, const float* __restrict__ W,
    float* __restrict__ C, int nrows)
{
    __shared__ float sA[16][64];     // transposed: sA[k][r]
    __shared__ float sW[16][128];
    int tid = threadIdx.x;
    int tx = tid & 15, ty = tid >> 4;
    int row0 = blockIdx.x * 64;

    float acc[4][8];
#pragma unroll
    for (int i = 0; i < 4; i++)
#pragma unroll
        for (int j = 0; j < 8; j++) acc[i][j] = 0.f;

    for (int kt = 0; kt < 128; kt += 16) {
        {
            int r = tid >> 2;
            int k4 = (tid & 3) * 4;
            int gr = row0 + r;
            float4 v = (gr < nrows) ? *(const float4*)(A + (size_t)gr * 128 + kt + k4)
                                    : make_float4(0.f, 0.f, 0.f, 0.f);
            sA[k4 + 0][r] = v.x; sA[k4 + 1][r] = v.y;
            sA[k4 + 2][r] = v.z; sA[k4 + 3][r] = v.w;
        }
#pragma unroll
        for (int i = 0; i < 2; i++) {
            int t = tid + i * 256;
            int kr = t >> 5;
            int c4 = (t & 31) * 4;
            *(float4*)&sW[kr][c4] = *(const float4*)(W + (size_t)(kt + kr) * 128 + c4);
        }
        __syncthreads();

#pragma unroll
        for (int k = 0; k < 16; k++) {
            float4 av = *(float4*)&sA[k][ty * 4];
            float4 w0 = *(float4*)&sW[k][tx * 4];
            float4 w1 = *(float4*)&sW[k][64 + tx * 4];
            float w[8] = {w0.x, w0.y, w0.z, w0.w, w1.x, w1.y, w1.z, w1.w};
            float a[4] = {av.x, av.y, av.z, av.w};
#pragma unroll
            for (int i = 0; i < 4; i++)
#pragma unroll
                for (int j = 0; j < 8; j++) acc[i][j] += a[i] * w[j];
        }
        __syncthreads();
    }

#pragma unroll
    for (int i = 0; i < 4; i++) {
        int gr = row0 + ty * 4 + i;
        if (gr < nrows) {
            *(float4*)(C + (size_t)gr * 128 + tx * 4) =
                make_float4(acc[i][0], acc[i][1], acc[i][2], acc[i][3]);
            *(float4*)(C + (size_t)gr * 128 + 64 + tx * 4) =
                make_float4(acc[i][4], acc[i][5], acc[i][6], acc[i][7]);
        }
    }
}

// ---------------- SGEMM: C[n,40] = A[n,128] @ W[128,40] ----------------
__global__ __launch_bounds__(256) void gemm40(
    const float* __restrict__ A, const float* __restrict__ W,
    float* __restrict__ C, int nrows)
{
    __shared__ float sA[16][64];
    __shared__ float sW[16][40];
    int tid = threadIdx.x;
    int tx = tid & 15, ty = tid >> 4;
    int row0 = blockIdx.x * 64;

    float acc[4][3];
#pragma unroll
    for (int i = 0; i < 4; i++)
#pragma unroll
        for (int j = 0; j < 3; j++) acc[i][j] = 0.f;

    for (int kt = 0; kt < 128; kt += 16) {
        {
            int r = tid >> 2;
            int k4 = (tid & 3) * 4;
            int gr = row0 + r;
            float4 v = (gr < nrows) ? *(const float4*)(A + (size_t)gr * 128 + kt + k4)
                                    : make_float4(0.f, 0.f, 0.f, 0.f);
            sA[k4 + 0][r] = v.x; sA[k4 + 1][r] = v.y;
            sA[k4 + 2][r] = v.z; sA[k4 + 3][r] = v.w;
        }
        for (int t = tid; t < 16 * 40; t += 256) {
            int kr = t / 40, c = t % 40;
            sW[kr][c] = W[(size_t)(kt + kr) * 40 + c];
        }
        __syncthreads();

#pragma unroll
        for (int k = 0; k < 16; k++) {
            float4 av = *(float4*)&sA[k][ty * 4];
            float a[4] = {av.x, av.y, av.z, av.w};
            float w0 = sW[k][tx];
            float w1 = sW[k][tx + 16];
            float w2 = (tx < 8) ? sW[k][tx + 32] : 0.f;
#pragma unroll
            for (int i = 0; i < 4; i++) {
                acc[i][0] += a[i] * w0;
                acc[i][1] += a[i] * w1;
                acc[i][2] += a[i] * w2;
            }
        }
        __syncthreads();
    }

#pragma unroll
    for (int i = 0; i < 4; i++) {
        int gr = row0 + ty * 4 + i;
        if (gr >= nrows) continue;
        C[(size_t)gr * 40 + tx]      = acc[i][0];
        C[(size_t)gr * 40 + tx + 16] = acc[i][1];
        if (tx < 8) C[(size_t)gr * 40 + tx + 32] = acc[i][2];
    }
}

// ---------------- pre-scale h by dinv[row], and init out with bias + self-loop ----------------
// out[r] = bias + h[r]*dinv[r]^2 ; hs[r] = h[r]*dinv[r]  (so edge kernel only needs dinv[dst])
template <int D>
__global__ void k_prep(float* __restrict__ h, const float* __restrict__ bias,
                       const float* __restrict__ dinv, float* __restrict__ out, int n)
{
    const int D4 = D / 4;
    int idx = blockIdx.x * blockDim.x + threadIdx.x;
    if (idx >= n * D4) return;
    int r = idx / D4;
    int g = (idx % D4) * 4;
    float di = dinv[r];
    float4 hv = *(const float4*)(h + (size_t)r * D + g);
    float4 bv = *(const float4*)(bias + g);
    // self-loop contribution uses dinv^2
    float4 o = make_float4(bv.x + hv.x * di * di, bv.y + hv.y * di * di,
                           bv.z + hv.z * di * di, bv.w + hv.w * di * di);
    *(float4*)(out + (size_t)r * D + g) = o;
    // overwrite h with pre-scaled version for the edge pass
    float4 hs = make_float4(hv.x * di, hv.y * di, hv.z * di, hv.w * di);
    *(float4*)(h + (size_t)r * D + g) = hs;
}

// ---------------- aggregation: edge scatter-add ----------------
// one (edge, float4-group) pair per thread; consecutive threads cover one edge's row
template <int D>
__global__ void k_edge(const float* __restrict__ h, const int* __restrict__ src,
                       const int* __restrict__ dst, const float* __restrict__ dinv,
                       float* __restrict__ out, int E)
{
    const int D4 = D / 4;
    int idx = blockIdx.x * blockDim.x + threadIdx.x;
    if (idx >= E * D4) return;
    int e = idx / D4;
    int g = (idx % D4) * 4;
    int s = __ldg(src + e);
    int d = __ldg(dst + e);
    float nrm = __ldg(dinv + d);                 // src dinv already folded into h
    float4 v = __ldg((const float4*)(h + (size_t)s * D + g));
    float* o = out + (size_t)d * D + g;
    atomicAdd(o + 0, v.x * nrm);
    atomicAdd(o + 1, v.y * nrm);
    atomicAdd(o + 2, v.z * nrm);
    atomicAdd(o + 3, v.w * nrm);
}

// ---------------- batchnorm ----------------
__global__ void k_bnzero() {
    int c = threadIdx.x;
    g_sum[c] = 0.f;
    g_sq[c] = 0.f;
}

__global__ void k_bnstats(const float* __restrict__ h, int n) {
    int c = threadIdx.x;                         // 128 threads, one column each
    int r0 = blockIdx.x * 256;
    int r1 = min(r0 + 256, n);
    float s = 0.f, q = 0.f;
    for (int r = r0; r < r1; r++) {
        float v = h[(size_t)r * DH + c];
        s += v;
        q += v * v;
    }
    atomicAdd(&g_sum[c], s);
    atomicAdd(&g_sq[c], q);
}

__global__ void k_bnfin(const float* __restrict__ gamma, const float* __restrict__ beta, int n) {
    int c = threadIdx.x;
    float inv_n = 1.0f / (float)n;
    float mu = g_sum[c] * inv_n;
    float var = g_sq[c] * inv_n - mu * mu;
    float rstd = rsqrtf(var + 1e-5f);
    float a = gamma[c] * rstd;
    g_bna[c] = a;
    g_bnb[c] = beta[c] - mu * a;
}

__global__ void k_bnapply(float* __restrict__ h, int n) {
    int idx = blockIdx.x * blockDim.x + threadIdx.x;
    if (idx >= n * 32) return;
    int r = idx >> 5;
    int g = (idx & 31) * 4;
    float4 v = *(float4*)(h + (size_t)r * DH + g);
    float4 a = *(const float4*)&g_bna[g];
    float4 b = *(const float4*)&g_bnb[g];
    v.x = fmaxf(v.x * a.x + b.x, 0.f);
    v.y = fmaxf(v.y * a.y + b.y, 0.f);
    v.z = fmaxf(v.z * a.z + b.z, 0.f);
    v.w = fmaxf(v.w * a.w + b.w, 0.f);
    *(float4*)(h + (size_t)r * DH + g) = v;
}

// ---------------- log_softmax over 40 cols, in place ----------------
__global__ void k_lsm(float* __restrict__ out, int n) {
    int warp = (blockIdx.x * blockDim.x + threadIdx.x) >> 5;
    int lane = threadIdx.x & 31;
    if (warp >= n) return;
    float* row = out + (size_t)warp * 40;
    float a = row[lane];
    float b = (lane < 8) ? row[lane + 32] : -INFINITY;
    float m = fmaxf(a, b);
#pragma unroll
    for (int o = 16; o > 0; o >>= 1)
        m = fmaxf(m, __shfl_xor_sync(0xffffffffu, m, o));
    float s = expf(a - m) + ((lane < 8) ? expf(b - m) : 0.f);
#pragma unroll
    for (int o = 16; o > 0; o >>= 1)
        s += __shfl_xor_sync(0xffffffffu, s, o);
    float l = m + logf(s);
    row[lane] = a - l;
    if (lane < 8) row[lane + 32] = b - l;
}

// ---------------- host orchestration ----------------
extern "C" void kernel_launch(void* const* d_in, const int* in_sizes, int n_in,
                              void* d_out, int out_size)
{
    const float* x   = (const float*)d_in[0];
    const int*   ei  = (const int*)d_in[1];
    const float* W0  = (const float*)d_in[2];
    const float* b0  = (const float*)d_in[3];
    const float* W1  = (const float*)d_in[4];
    const float* b1  = (const float*)d_in[5];
    const float* W2  = (const float*)d_in[6];
    const float* b2  = (const float*)d_in[7];
    const float* g0  = (const float*)d_in[8];
    const float* bt0 = (const float*)d_in[9];
    const float* g1  = (const float*)d_in[10];
    const float* bt1 = (const float*)d_in[11];
    float* out = (float*)d_out;

    int N = in_sizes[0] / DH;
    int E = in_sizes[1] / 2;
    const int* src = ei;
    const int* dst = ei + E;

    float *dinv, *h1, *h2;
    cudaGetSymbolAddress((void**)&dinv, g_dinv);
    cudaGetSymbolAddress((void**)&h1, g_h1);
    cudaGetSymbolAddress((void**)&h2, g_h2);

    // degree / normalization
    k_deg_init<<<(N + 255) / 256, 256>>>(dinv, N);
    k_deg_acc<<<(E + 255) / 256, 256>>>(dst, dinv, E);
    k_rsqrt<<<(N + 255) / 256, 256>>>(dinv, N);

    int gemm_blocks = (N + 63) / 64;
    int e128_blocks = (E * 32 + 255) / 256;
    int n128_blocks = (N * 32 + 255) / 256;

    // ---- layer 0: conv -> bn -> relu ----
    gemm128<<<gemm_blocks, 256>>>(x, W0, h1, N);
    k_prep<DH><<<n128_blocks, 256>>>(h1, b0, dinv, h2, N);
    k_edge<DH><<<e128_blocks, 256>>>(h1, src, dst, dinv, h2, E);
    k_bnzero<<<1, 128>>>();
    k_bnstats<<<(N + 255) / 256, 128>>>(h2, N);
    k_bnfin<<<1, 128>>>(g0, bt0, N);
    k_bnapply<<<n128_blocks, 256>>>(h2, N);

    // ---- layer 1: conv -> bn -> relu ----
    gemm128<<<gemm_blocks, 256>>>(h2, W1, h1, N);
    k_prep<DH><<<n128_blocks, 256>>>(h1, b1, dinv, h2, N);
    k_edge<DH><<<e128_blocks, 256>>>(h1, src, dst, dinv, h2, E);
    k_bnzero<<<1, 128>>>();
    k_bnstats<<<(N + 255) / 256, 128>>>(h2, N);
    k_bnfin<<<1, 128>>>(g1, bt1, N);
    k_bnapply<<<n128_blocks, 256>>>(h2, N);

    // ---- layer 2: conv -> log_softmax ----
    gemm40<<<gemm_blocks, 256>>>(h2, W2, h1, N);   // reuse h1 as [N,40]
    k_prep<40><<<(N * 10 + 255) / 256, 256>>>(h1, b2, dinv, out, N);
    k_edge<40><<<(E * 10 + 255) / 256, 256>>>(h1, src, dst, dinv, out, E);
    k_lsm<<<(N + 7) / 8, 256>>>(out, N);
}

// round 3
// speedup vs baseline: 1.7059x; 1.7059x over previous
#include <cuda_runtime.h>
#include <math.h>

#define DH 128
#define NMAX 50016
#define EMAX 800000

// ---------------- scratch (device globals; no allocation allowed) ----------------
__device__ float g_dinv[NMAX];
__device__ int   g_deg[NMAX];
__device__ int   g_rowptr[NMAX + 1];
__device__ int   g_cursor[NMAX];
__device__ int   g_adj[EMAX];
__device__ float g_h1[(size_t)NMAX * DH];   // dinv-scaled transformed features
__device__ float g_h2[(size_t)NMAX * DH];   // aggregated features
__device__ float g_sum[DH];
__device__ float g_sq[DH];
__device__ float g_bna[DH];                 // a = gamma * rstd
__device__ float g_bnb[DH];                 // b = beta - mu * a

// ---------------- CSR build ----------------
__global__ void k_zero_deg(int* deg, int n) {
    int i = blockIdx.x * blockDim.x + threadIdx.x;
    if (i < n) deg[i] = 0;
}

__global__ void k_count(const int* __restrict__ dst, int* deg, int E) {
    int e = blockIdx.x * blockDim.x + threadIdx.x;
    if (e < E) atomicAdd(&deg[dst[e]], 1);
}

// single block, 1024 threads: exclusive scan of deg -> rowptr/cursor, and dinv
__global__ __launch_bounds__(1024) void k_scan(const int* __restrict__ deg,
                                               int* rowptr, int* cursor,
                                               float* dinv, int n)
{
    __shared__ int sm[1024];
    const int T = 1024;
    int tid = threadIdx.x;
    int chunk = (n + T - 1) / T;
    int beg = tid * chunk;
    int end = min(beg + chunk, n);
    if (beg > n) beg = n;
    if (end < beg) end = beg;

    int s = 0;
    for (int i = beg; i < end; i++) s += deg[i];
    sm[tid] = s;
    __syncthreads();
    // Hillis-Steele inclusive scan
    for (int off = 1; off < T; off <<= 1) {
        int v = (tid >= off) ? sm[tid - off] : 0;
        __syncthreads();
        sm[tid] += v;
        __syncthreads();
    }
    int run = sm[tid] - s;                  // exclusive prefix of this chunk
    for (int i = beg; i < end; i++) {
        int d = deg[i];
        rowptr[i] = run;
        cursor[i] = run;
        dinv[i] = rsqrtf((float)d + 1.0f);  // +1 self-loop
        run += d;
    }
    if (tid == T - 1) rowptr[n] = sm[T - 1];
}

__global__ void k_fill(const int* __restrict__ src, const int* __restrict__ dst,
                       int* cursor, int* adj, int E)
{
    int e = blockIdx.x * blockDim.x + threadIdx.x;
    if (e < E) {
        int d = dst[e];
        int p = atomicAdd(&cursor[d], 1);
        adj[p] = src[e];
    }
}

// ---------------- SGEMM: C[n,128] = op(A)[n,128] @ W[128,128], C scaled by dinv[row] ----------------
// op(A) = BN ? relu(A*bna+bnb) : A   (per-column affine)
template <bool BN>
__global__ __launch_bounds__(256) void gemm128(
    const float* __restrict__ A, const float* __restrict__ W,
    float* __restrict__ C, const float* __restrict__ dinv,
    const float* __restrict__ bna, const float* __restrict__ bnb, int nrows)
{
    __shared__ float sA[16][64];     // transposed: sA[k][r]
    __shared__ float sW[16][128];
    int tid = threadIdx.x;
    int tx = tid & 15, ty = tid >> 4;
    int row0 = blockIdx.x * 64;

    float acc[4][8];
#pragma unroll
    for (int i = 0; i < 4; i++)
#pragma unroll
        for (int j = 0; j < 8; j++) acc[i][j] = 0.f;

    for (int kt = 0; kt < 128; kt += 16) {
        {
            int r = tid >> 2;
            int k4 = (tid & 3) * 4;
            int gr = row0 + r;
            float4 v = (gr < nrows) ? *(const float4*)(A + (size_t)gr * 128 + kt + k4)
                                    : make_float4(0.f, 0.f, 0.f, 0.f);
            if (BN) {
                int c = kt + k4;
                v.x = fmaxf(v.x * bna[c + 0] + bnb[c + 0], 0.f);
                v.y = fmaxf(v.y * bna[c + 1] + bnb[c + 1], 0.f);
                v.z = fmaxf(v.z * bna[c + 2] + bnb[c + 2], 0.f);
                v.w = fmaxf(v.w * bna[c + 3] + bnb[c + 3], 0.f);
            }
            sA[k4 + 0][r] = v.x; sA[k4 + 1][r] = v.y;
            sA[k4 + 2][r] = v.z; sA[k4 + 3][r] = v.w;
        }
#pragma unroll
        for (int i = 0; i < 2; i++) {
            int t = tid + i * 256;
            int kr = t >> 5;
            int c4 = (t & 31) * 4;
            *(float4*)&sW[kr][c4] = *(const float4*)(W + (size_t)(kt + kr) * 128 + c4);
        }
        __syncthreads();

#pragma unroll
        for (int k = 0; k < 16; k++) {
            float4 av = *(float4*)&sA[k][ty * 4];
            float4 w0 = *(float4*)&sW[k][tx * 4];
            float4 w1 = *(float4*)&sW[k][64 + tx * 4];
            float w[8] = {w0.x, w0.y, w0.z, w0.w, w1.x, w1.y, w1.z, w1.w};
            float a[4] = {av.x, av.y, av.z, av.w};
#pragma unroll
            for (int i = 0; i < 4; i++)
#pragma unroll
                for (int j = 0; j < 8; j++) acc[i][j] += a[i] * w[j];
        }
        __syncthreads();
    }

#pragma unroll
    for (int i = 0; i < 4; i++) {
        int gr = row0 + ty * 4 + i;
        if (gr < nrows) {
            float di = dinv[gr];
            *(float4*)(C + (size_t)gr * 128 + tx * 4) =
                make_float4(acc[i][0] * di, acc[i][1] * di, acc[i][2] * di, acc[i][3] * di);
            *(float4*)(C + (size_t)gr * 128 + 64 + tx * 4) =
                make_float4(acc[i][4] * di, acc[i][5] * di, acc[i][6] * di, acc[i][7] * di);
        }
    }
}

// ---------------- SGEMM: C[n,40] = relu(A*bna+bnb)[n,128] @ W[128,40], scaled by dinv ----------------
__global__ __launch_bounds__(256) void gemm40(
    const float* __restrict__ A, const float* __restrict__ W,
    float* __restrict__ C, const float* __restrict__ dinv,
    const float* __restrict__ bna, const float* __restrict__ bnb, int nrows)
{
    __shared__ float sA[16][64];
    __shared__ float sW[16][40];
    int tid = threadIdx.x;
    int tx = tid & 15, ty = tid >> 4;
    int row0 = blockIdx.x * 64;

    float acc[4][3];
#pragma unroll
    for (int i = 0; i < 4; i++)
#pragma unroll
        for (int j = 0; j < 3; j++) acc[i][j] = 0.f;

    for (int kt = 0; kt < 128; kt += 16) {
        {
            int r = tid >> 2;
            int k4 = (tid & 3) * 4;
            int gr = row0 + r;
            float4 v = (gr < nrows) ? *(const float4*)(A + (size_t)gr * 128 + kt + k4)
                                    : make_float4(0.f, 0.f, 0.f, 0.f);
            int c = kt + k4;
            v.x = fmaxf(v.x * bna[c + 0] + bnb[c + 0], 0.f);
            v.y = fmaxf(v.y * bna[c + 1] + bnb[c + 1], 0.f);
            v.z = fmaxf(v.z * bna[c + 2] + bnb[c + 2], 0.f);
            v.w = fmaxf(v.w * bna[c + 3] + bnb[c + 3], 0.f);
            sA[k4 + 0][r] = v.x; sA[k4 + 1][r] = v.y;
            sA[k4 + 2][r] = v.z; sA[k4 + 3][r] = v.w;
        }
        for (int t = tid; t < 16 * 40; t += 256) {
            int kr = t / 40, c = t % 40;
            sW[kr][c] = W[(size_t)(kt + kr) * 40 + c];
        }
        __syncthreads();

#pragma unroll
        for (int k = 0; k < 16; k++) {
            float4 av = *(float4*)&sA[k][ty * 4];
            float a[4] = {av.x, av.y, av.z, av.w};
            float w0 = sW[k][tx];
            float w1 = sW[k][tx + 16];
            float w2 = (tx < 8) ? sW[k][tx + 32] : 0.f;
#pragma unroll
            for (int i = 0; i < 4; i++) {
                acc[i][0] += a[i] * w0;
                acc[i][1] += a[i] * w1;
                acc[i][2] += a[i] * w2;
            }
        }
        __syncthreads();
    }

#pragma unroll
    for (int i = 0; i < 4; i++) {
        int gr = row0 + ty * 4 + i;
        if (gr >= nrows) continue;
        float di = dinv[gr];
        C[(size_t)gr * 40 + tx]      = acc[i][0] * di;
        C[(size_t)gr * 40 + tx + 16] = acc[i][1] * di;
        if (tx < 8) C[(size_t)gr * 40 + tx + 32] = acc[i][2] * di;
    }
}

// ---------------- CSR gather aggregation, D=128: one warp per node ----------------
// out[d] = bias + dinv[d] * (hs[d] + sum_{s in N(d)} hs[s]);  optional BN stats accumulation
template <bool STATS>
__global__ __launch_bounds__(256) void k_agg128(
    const float* __restrict__ hs, const int* __restrict__ rowptr,
    const int* __restrict__ adj, const float* __restrict__ dinv,
    const float* __restrict__ bias, float* __restrict__ out, int n)
{
    __shared__ float ssum[DH];
    __shared__ float ssq[DH];
    int tid = threadIdx.x;
    if (STATS) {
        if (tid < DH) { ssum[tid] = 0.f; ssq[tid] = 0.f; }
        __syncthreads();
    }
    int warp = tid >> 5, lane = tid & 31;
    int node = blockIdx.x * 8 + warp;
    if (node < n) {
        int g = lane * 4;
        int beg = __ldg(rowptr + node);
        int end = __ldg(rowptr + node + 1);
        float4 acc = __ldg((const float4*)(hs + (size_t)node * DH + g));   // self-loop
        int j = beg;
        for (; j + 4 <= end; j += 4) {
            int s0 = __ldg(adj + j + 0);
            int s1 = __ldg(adj + j + 1);
            int s2 = __ldg(adj + j + 2);
            int s3 = __ldg(adj + j + 3);
            float4 v0 = __ldg((const float4*)(hs + (size_t)s0 * DH + g));
            float4 v1 = __ldg((const float4*)(hs + (size_t)s1 * DH + g));
            float4 v2 = __ldg((const float4*)(hs + (size_t)s2 * DH + g));
            float4 v3 = __ldg((const float4*)(hs + (size_t)s3 * DH + g));
            acc.x += (v0.x + v1.x) + (v2.x + v3.x);
            acc.y += (v0.y + v1.y) + (v2.y + v3.y);
            acc.z += (v0.z + v1.z) + (v2.z + v3.z);
            acc.w += (v0.w + v1.w) + (v2.w + v3.w);
        }
        for (; j < end; j++) {
            int s = __ldg(adj + j);
            float4 v = __ldg((const float4*)(hs + (size_t)s * DH + g));
            acc.x += v.x; acc.y += v.y; acc.z += v.z; acc.w += v.w;
        }
        float di = dinv[node];
        float4 bv = __ldg((const float4*)(bias + g));
        float4 o = make_float4(bv.x + acc.x * di, bv.y + acc.y * di,
                               bv.z + acc.z * di, bv.w + acc.w * di);
        *(float4*)(out + (size_t)node * DH + g) = o;
        if (STATS) {
            atomicAdd(&ssum[g + 0], o.x); atomicAdd(&ssq[g + 0], o.x * o.x);
            atomicAdd(&ssum[g + 1], o.y); atomicAdd(&ssq[g + 1], o.y * o.y);
            atomicAdd(&ssum[g + 2], o.z); atomicAdd(&ssq[g + 2], o.z * o.z);
            atomicAdd(&ssum[g + 3], o.w); atomicAdd(&ssq[g + 3], o.w * o.w);
        }
    }
    if (STATS) {
        __syncthreads();
        if (tid < DH) {
            atomicAdd(&g_sum[tid], ssum[tid]);
            atomicAdd(&g_sq[tid], ssq[tid]);
        }
    }
}

// ---------------- CSR gather aggregation, D=40: one warp per node, lanes 0-9 ----------------
__global__ __launch_bounds__(256) void k_agg40(
    const float* __restrict__ hs, const int* __restrict__ rowptr,
    const int* __restrict__ adj, const float* __restrict__ dinv,
    const float* __restrict__ bias, float* __restrict__ out, int n)
{
    int tid = threadIdx.x;
    int warp = tid >> 5, lane = tid & 31;
    int node = blockIdx.x * 8 + warp;
    if (node >= n || lane >= 10) return;
    int g = lane * 4;
    int beg = __ldg(rowptr + node);
    int end = __ldg(rowptr + node + 1);
    float4 acc = __ldg((const float4*)(hs + (size_t)node * 40 + g));
    int j = beg;
    for (; j + 4 <= end; j += 4) {
        int s0 = __ldg(adj + j + 0);
        int s1 = __ldg(adj + j + 1);
        int s2 = __ldg(adj + j + 2);
        int s3 = __ldg(adj + j + 3);
        float4 v0 = __ldg((const float4*)(hs + (size_t)s0 * 40 + g));
        float4 v1 = __ldg((const float4*)(hs + (size_t)s1 * 40 + g));
        float4 v2 = __ldg((const float4*)(hs + (size_t)s2 * 40 + g));
        float4 v3 = __ldg((const float4*)(hs + (size_t)s3 * 40 + g));
        acc.x += (v0.x + v1.x) + (v2.x + v3.x);
        acc.y += (v0.y + v1.y) + (v2.y + v3.y);
        acc.z += (v0.z + v1.z) + (v2.z + v3.z);
        acc.w += (v0.w + v1.w) + (v2.w + v3.w);
    }
    for (; j < end; j++) {
        int s = __ldg(adj + j);
        float4 v = __ldg((const float4*)(hs + (size_t)s * 40 + g));
        acc.x += v.x; acc.y += v.y; acc.z += v.z; acc.w += v.w;
    }
    float di = dinv[node];
    float4 bv = __ldg((const float4*)(bias + g));
    *(float4*)(out + (size_t)node * 40 + g) =
        make_float4(bv.x + acc.x * di, bv.y + acc.y * di,
                    bv.z + acc.z * di, bv.w + acc.w * di);
}

// ---------------- batchnorm finalize ----------------
__global__ void k_bnzero() {
    int c = threadIdx.x;
    g_sum[c] = 0.f;
    g_sq[c] = 0.f;
}

__global__ void k_bnfin(const float* __restrict__ gamma, const float* __restrict__ beta, int n) {
    int c = threadIdx.x;
    float inv_n = 1.0f / (float)n;
    float mu = g_sum[c] * inv_n;
    float var = g_sq[c] * inv_n - mu * mu;
    float rstd = rsqrtf(var + 1e-5f);
    float a = gamma[c] * rstd;
    g_bna[c] = a;
    g_bnb[c] = beta[c] - mu * a;
}

// ---------------- log_softmax over 40 cols, in place ----------------
__global__ void k_lsm(float* __restrict__ out, int n) {
    int warp = (blockIdx.x * blockDim.x + threadIdx.x) >> 5;
    int lane = threadIdx.x & 31;
    if (warp >= n) return;
    float* row = out + (size_t)warp * 40;
    float a = row[lane];
    float b = (lane < 8) ? row[lane + 32] : -INFINITY;
    float m = fmaxf(a, b);
#pragma unroll
    for (int o = 16; o > 0; o >>= 1)
        m = fmaxf(m, __shfl_xor_sync(0xffffffffu, m, o));
    float s = expf(a - m) + ((lane < 8) ? expf(b - m) : 0.f);
#pragma unroll
    for (int o = 16; o > 0; o >>= 1)
        s += __shfl_xor_sync(0xffffffffu, s, o);
    float l = m + logf(s);
    row[lane] = a - l;
    if (lane < 8) row[lane + 32] = b - l;
}

// ---------------- host orchestration ----------------
extern "C" void kernel_launch(void* const* d_in, const int* in_sizes, int n_in,
                              void* d_out, int out_size)
{
    const float* x   = (const float*)d_in[0];
    const int*   ei  = (const int*)d_in[1];
    const float* W0  = (const float*)d_in[2];
    const float* b0  = (const float*)d_in[3];
    const float* W1  = (const float*)d_in[4];
    const float* b1  = (const float*)d_in[5];
    const float* W2  = (const float*)d_in[6];
    const float* b2  = (const float*)d_in[7];
    const float* g0  = (const float*)d_in[8];
    const float* bt0 = (const float*)d_in[9];
    const float* g1  = (const float*)d_in[10];
    const float* bt1 = (const float*)d_in[11];
    float* out = (float*)d_out;

    int N = in_sizes[0] / DH;
    int E = in_sizes[1] / 2;
    const int* src = ei;
    const int* dst = ei + E;

    float *dinv, *h1, *h2, *bna, *bnb;
    int *deg, *rowptr, *cursor, *adj;
    cudaGetSymbolAddress((void**)&dinv, g_dinv);
    cudaGetSymbolAddress((void**)&h1, g_h1);
    cudaGetSymbolAddress((void**)&h2, g_h2);
    cudaGetSymbolAddress((void**)&bna, g_bna);
    cudaGetSymbolAddress((void**)&bnb, g_bnb);
    cudaGetSymbolAddress((void**)&deg, g_deg);
    cudaGetSymbolAddress((void**)&rowptr, g_rowptr);
    cudaGetSymbolAddress((void**)&cursor, g_cursor);
    cudaGetSymbolAddress((void**)&adj, g_adj);

    // ---- CSR build (once) ----
    k_zero_deg<<<(N + 255) / 256, 256>>>(deg, N);
    k_count<<<(E + 255) / 256, 256>>>(dst, deg, E);
    k_scan<<<1, 1024>>>(deg, rowptr, cursor, dinv, N);
    k_fill<<<(E + 255) / 256, 256>>>(src, dst, cursor, adj, E);

    int gemm_blocks = (N + 63) / 64;
    int agg_blocks  = (N + 7) / 8;

    // ---- layer 0: conv -> bn stats ----
    gemm128<false><<<gemm_blocks, 256>>>(x, W0, h1, dinv, nullptr, nullptr, N);
    k_bnzero<<<1, 128>>>();
    k_agg128<true><<<agg_blocks, 256>>>(h1, rowptr, adj, dinv, b0, h2, N);
    k_bnfin<<<1, 128>>>(g0, bt0, N);

    // ---- layer 1: (bn0+relu fused into gemm) conv -> bn stats ----
    gemm128<true><<<gemm_blocks, 256>>>(h2, W1, h1, dinv, bna, bnb, N);
    k_bnzero<<<1, 128>>>();
    k_agg128<true><<<agg_blocks, 256>>>(h1, rowptr, adj, dinv, b1, h2, N);
    k_bnfin<<<1, 128>>>(g1, bt1, N);

    // ---- layer 2: (bn1+relu fused into gemm) conv -> log_softmax ----
    gemm40<<<gemm_blocks, 256>>>(h2, W2, h1, dinv, bna, bnb, N);
    k_agg40<<<agg_blocks, 256>>>(h1, rowptr, adj, dinv, b2, out, N);
    k_lsm<<<(N + 7) / 8, 256>>>(out, N);
}

// round 4
// speedup vs baseline: 2.0112x; 1.1790x over previous
#include <cuda_runtime.h>
#include <math.h>

#define DH 128
#define NMAX 50016
#define EMAX 800000

// ---------------- scratch (device globals; no allocation allowed) ----------------
__device__ float g_dinv[NMAX];
__device__ int   g_deg[NMAX];
__device__ int   g_rowptr[NMAX + 1];
__device__ int   g_cursor[NMAX];
__device__ int   g_adj[EMAX];
__device__ float g_h1[(size_t)NMAX * DH];   // dinv-scaled transformed features
__device__ float g_h2[(size_t)NMAX * DH];   // aggregated features
__device__ float g_sum[DH];
__device__ float g_sq[DH];
__device__ float g_bna[DH];                 // a = gamma * rstd
__device__ float g_bnb[DH];                 // b = beta - mu * a

// ---------------- CSR build ----------------
__global__ void k_zero_deg(int* deg, int n) {
    int i = blockIdx.x * blockDim.x + threadIdx.x;
    if (i < n) deg[i] = 0;
}

__global__ void k_count(const int* __restrict__ dst, int* deg, int E) {
    int e = blockIdx.x * blockDim.x + threadIdx.x;
    if (e < E) atomicAdd(&deg[dst[e]], 1);
}

// single block, 1024 threads: exclusive scan of deg -> rowptr/cursor, and dinv
__global__ __launch_bounds__(1024) void k_scan(const int* __restrict__ deg,
                                               int* rowptr, int* cursor,
                                               float* dinv, int n)
{
    __shared__ int sm[1024];
    const int T = 1024;
    int tid = threadIdx.x;
    int chunk = (n + T - 1) / T;
    int beg = tid * chunk;
    int end = min(beg + chunk, n);
    if (beg > n) beg = n;
    if (end < beg) end = beg;

    int s = 0;
    for (int i = beg; i < end; i++) s += deg[i];
    sm[tid] = s;
    __syncthreads();
    for (int off = 1; off < T; off <<= 1) {
        int v = (tid >= off) ? sm[tid - off] : 0;
        __syncthreads();
        sm[tid] += v;
        __syncthreads();
    }
    int run = sm[tid] - s;                  // exclusive prefix of this chunk
    for (int i = beg; i < end; i++) {
        int d = deg[i];
        rowptr[i] = run;
        cursor[i] = run;
        dinv[i] = rsqrtf((float)d + 1.0f);  // +1 self-loop
        run += d;
    }
    if (tid == T - 1) rowptr[n] = sm[T - 1];
}

__global__ void k_fill(const int* __restrict__ src, const int* __restrict__ dst,
                       int* cursor, int* adj, int E)
{
    int e = blockIdx.x * blockDim.x + threadIdx.x;
    if (e < E) {
        int d = dst[e];
        int p = atomicAdd(&cursor[d], 1);
        adj[p] = src[e];
    }
}

// ---------------- SGEMM: C[n,128] = op(A)[n,128] @ W[128,128], C scaled by dinv[row] ----------------
// op(A) = BN ? relu(A*bna+bnb) : A.  Block 0 also zeroes the BN-stat accumulators
// for the aggregation kernel that runs AFTER this gemm (safe: launches serialize).
template <bool BN>
__global__ __launch_bounds__(256) void gemm128(
    const float* __restrict__ A, const float* __restrict__ W,
    float* __restrict__ C, const float* __restrict__ dinv,
    const float* __restrict__ bna, const float* __restrict__ bnb, int nrows)
{
    if (blockIdx.x == 0 && threadIdx.x < DH) {
        g_sum[threadIdx.x] = 0.f;
        g_sq[threadIdx.x] = 0.f;
    }
    __shared__ float sA[16][64];     // transposed: sA[k][r]
    __shared__ float sW[16][128];
    int tid = threadIdx.x;
    int tx = tid & 15, ty = tid >> 4;
    int row0 = blockIdx.x * 64;

    float acc[4][8];
#pragma unroll
    for (int i = 0; i < 4; i++)
#pragma unroll
        for (int j = 0; j < 8; j++) acc[i][j] = 0.f;

    for (int kt = 0; kt < 128; kt += 16) {
        {
            int r = tid >> 2;
            int k4 = (tid & 3) * 4;
            int gr = row0 + r;
            float4 v = (gr < nrows) ? *(const float4*)(A + (size_t)gr * 128 + kt + k4)
                                    : make_float4(0.f, 0.f, 0.f, 0.f);
            if (BN) {
                int c = kt + k4;
                v.x = fmaxf(v.x * bna[c + 0] + bnb[c + 0], 0.f);
                v.y = fmaxf(v.y * bna[c + 1] + bnb[c + 1], 0.f);
                v.z = fmaxf(v.z * bna[c + 2] + bnb[c + 2], 0.f);
                v.w = fmaxf(v.w * bna[c + 3] + bnb[c + 3], 0.f);
            }
            sA[k4 + 0][r] = v.x; sA[k4 + 1][r] = v.y;
            sA[k4 + 2][r] = v.z; sA[k4 + 3][r] = v.w;
        }
#pragma unroll
        for (int i = 0; i < 2; i++) {
            int t = tid + i * 256;
            int kr = t >> 5;
            int c4 = (t & 31) * 4;
            *(float4*)&sW[kr][c4] = *(const float4*)(W + (size_t)(kt + kr) * 128 + c4);
        }
        __syncthreads();

#pragma unroll
        for (int k = 0; k < 16; k++) {
            float4 av = *(float4*)&sA[k][ty * 4];
            float4 w0 = *(float4*)&sW[k][tx * 4];
            float4 w1 = *(float4*)&sW[k][64 + tx * 4];
            float w[8] = {w0.x, w0.y, w0.z, w0.w, w1.x, w1.y, w1.z, w1.w};
            float a[4] = {av.x, av.y, av.z, av.w};
#pragma unroll
            for (int i = 0; i < 4; i++)
#pragma unroll
                for (int j = 0; j < 8; j++) acc[i][j] += a[i] * w[j];
        }
        __syncthreads();
    }

#pragma unroll
    for (int i = 0; i < 4; i++) {
        int gr = row0 + ty * 4 + i;
        if (gr < nrows) {
            float di = dinv[gr];
            *(float4*)(C + (size_t)gr * 128 + tx * 4) =
                make_float4(acc[i][0] * di, acc[i][1] * di, acc[i][2] * di, acc[i][3] * di);
            *(float4*)(C + (size_t)gr * 128 + 64 + tx * 4) =
                make_float4(acc[i][4] * di, acc[i][5] * di, acc[i][6] * di, acc[i][7] * di);
        }
    }
}

// ---------------- SGEMM: C[n,40] = relu(A*bna+bnb)[n,128] @ W[128,40], scaled by dinv ----------------
__global__ __launch_bounds__(256) void gemm40(
    const float* __restrict__ A, const float* __restrict__ W,
    float* __restrict__ C, const float* __restrict__ dinv,
    const float* __restrict__ bna, const float* __restrict__ bnb, int nrows)
{
    __shared__ float sA[16][64];
    __shared__ float sW[16][40];
    int tid = threadIdx.x;
    int tx = tid & 15, ty = tid >> 4;
    int row0 = blockIdx.x * 64;

    float acc[4][3];
#pragma unroll
    for (int i = 0; i < 4; i++)
#pragma unroll
        for (int j = 0; j < 3; j++) acc[i][j] = 0.f;

    for (int kt = 0; kt < 128; kt += 16) {
        {
            int r = tid >> 2;
            int k4 = (tid & 3) * 4;
            int gr = row0 + r;
            float4 v = (gr < nrows) ? *(const float4*)(A + (size_t)gr * 128 + kt + k4)
                                    : make_float4(0.f, 0.f, 0.f, 0.f);
            int c = kt + k4;
            v.x = fmaxf(v.x * bna[c + 0] + bnb[c + 0], 0.f);
            v.y = fmaxf(v.y * bna[c + 1] + bnb[c + 1], 0.f);
            v.z = fmaxf(v.z * bna[c + 2] + bnb[c + 2], 0.f);
            v.w = fmaxf(v.w * bna[c + 3] + bnb[c + 3], 0.f);
            sA[k4 + 0][r] = v.x; sA[k4 + 1][r] = v.y;
            sA[k4 + 2][r] = v.z; sA[k4 + 3][r] = v.w;
        }
        for (int t = tid; t < 16 * 40; t += 256) {
            int kr = t / 40, c = t % 40;
            sW[kr][c] = W[(size_t)(kt + kr) * 40 + c];
        }
        __syncthreads();

#pragma unroll
        for (int k = 0; k < 16; k++) {
            float4 av = *(float4*)&sA[k][ty * 4];
            float a[4] = {av.x, av.y, av.z, av.w};
            float w0 = sW[k][tx];
            float w1 = sW[k][tx + 16];
            float w2 = (tx < 8) ? sW[k][tx + 32] : 0.f;
#pragma unroll
            for (int i = 0; i < 4; i++) {
                acc[i][0] += a[i] * w0;
                acc[i][1] += a[i] * w1;
                acc[i][2] += a[i] * w2;
            }
        }
        __syncthreads();
    }

#pragma unroll
    for (int i = 0; i < 4; i++) {
        int gr = row0 + ty * 4 + i;
        if (gr >= nrows) continue;
        float di = dinv[gr];
        C[(size_t)gr * 40 + tx]      = acc[i][0] * di;
        C[(size_t)gr * 40 + tx + 16] = acc[i][1] * di;
        if (tx < 8) C[(size_t)gr * 40 + tx + 32] = acc[i][2] * di;
    }
}

// ---------------- CSR gather aggregation, D=128 ----------------
// Grid-stride, one warp per node per step. Register BN stats + block-level reduce.
template <bool STATS>
__global__ __launch_bounds__(256) void k_agg128(
    const float* __restrict__ hs, const int* __restrict__ rowptr,
    const int* __restrict__ adj, const float* __restrict__ dinv,
    const float* __restrict__ bias, float* __restrict__ out, int n)
{
    int tid = threadIdx.x;
    int warp = tid >> 5, lane = tid & 31;
    int g = lane * 4;
    float4 bv = __ldg((const float4*)(bias + g));

    float s0 = 0.f, s1 = 0.f, s2 = 0.f, s3 = 0.f;
    float q0 = 0.f, q1 = 0.f, q2 = 0.f, q3 = 0.f;

    for (int node = blockIdx.x * 8 + warp; node < n; node += gridDim.x * 8) {
        int beg = __ldg(rowptr + node);
        int end = __ldg(rowptr + node + 1);
        float4 acc = __ldg((const float4*)(hs + (size_t)node * DH + g));   // self-loop
        int j = beg;
        for (; j + 8 <= end; j += 8) {
            int sx[8];
#pragma unroll
            for (int u = 0; u < 8; u++) sx[u] = __ldg(adj + j + u);
            float4 v[8];
#pragma unroll
            for (int u = 0; u < 8; u++)
                v[u] = __ldg((const float4*)(hs + (size_t)sx[u] * DH + g));
#pragma unroll
            for (int u = 0; u < 8; u++) {
                acc.x += v[u].x; acc.y += v[u].y;
                acc.z += v[u].z; acc.w += v[u].w;
            }
        }
        for (; j < end; j++) {
            int s = __ldg(adj + j);
            float4 v = __ldg((const float4*)(hs + (size_t)s * DH + g));
            acc.x += v.x; acc.y += v.y; acc.z += v.z; acc.w += v.w;
        }
        float di = dinv[node];
        float4 o = make_float4(bv.x + acc.x * di, bv.y + acc.y * di,
                               bv.z + acc.z * di, bv.w + acc.w * di);
        *(float4*)(out + (size_t)node * DH + g) = o;
        if (STATS) {
            s0 += o.x; q0 += o.x * o.x;
            s1 += o.y; q1 += o.y * o.y;
            s2 += o.z; q2 += o.z * o.z;
            s3 += o.w; q3 += o.w * o.w;
        }
    }

    if (STATS) {
        __shared__ float rsum[8][DH];
        __shared__ float rsq[8][DH];
        rsum[warp][g + 0] = s0; rsum[warp][g + 1] = s1;
        rsum[warp][g + 2] = s2; rsum[warp][g + 3] = s3;
        rsq[warp][g + 0] = q0; rsq[warp][g + 1] = q1;
        rsq[warp][g + 2] = q2; rsq[warp][g + 3] = q3;
        __syncthreads();
        if (tid < DH) {
            float a = 0.f, b = 0.f;
#pragma unroll
            for (int w = 0; w < 8; w++) { a += rsum[w][tid]; b += rsq[w][tid]; }
            atomicAdd(&g_sum[tid], a);
            atomicAdd(&g_sq[tid], b);
        }
    }
}

// ---------------- CSR gather aggregation D=40 + fused log_softmax ----------------
// one warp per node; lanes 0-9 hold the 40-wide row; softmax via warp shuffles
__global__ __launch_bounds__(256) void k_agg40(
    const float* __restrict__ hs, const int* __restrict__ rowptr,
    const int* __restrict__ adj, const float* __restrict__ dinv,
    const float* __restrict__ bias, float* __restrict__ out, int n)
{
    int tid = threadIdx.x;
    int warp = tid >> 5, lane = tid & 31;
    int node = blockIdx.x * 8 + warp;
    if (node >= n) return;

    float4 o = make_float4(0.f, 0.f, 0.f, 0.f);
    if (lane < 10) {
        int g = lane * 4;
        int beg = __ldg(rowptr + node);
        int end = __ldg(rowptr + node + 1);
        float4 acc = __ldg((const float4*)(hs + (size_t)node * 40 + g));
        int j = beg;
        for (; j + 8 <= end; j += 8) {
            int sx[8];
#pragma unroll
            for (int u = 0; u < 8; u++) sx[u] = __ldg(adj + j + u);
            float4 v[8];
#pragma unroll
            for (int u = 0; u < 8; u++)
                v[u] = __ldg((const float4*)(hs + (size_t)sx[u] * 40 + g));
#pragma unroll
            for (int u = 0; u < 8; u++) {
                acc.x += v[u].x; acc.y += v[u].y;
                acc.z += v[u].z; acc.w += v[u].w;
            }
        }
        for (; j < end; j++) {
            int s = __ldg(adj + j);
            float4 v = __ldg((const float4*)(hs + (size_t)s * 40 + g));
            acc.x += v.x; acc.y += v.y; acc.z += v.z; acc.w += v.w;
        }
        float di = dinv[node];
        float4 bvv = __ldg((const float4*)(bias + g));
        o = make_float4(bvv.x + acc.x * di, bvv.y + acc.y * di,
                        bvv.z + acc.z * di, bvv.w + acc.w * di);
    }

    // fused log-softmax over the 40 values held by lanes 0-9
    float m = (lane < 10) ? fmaxf(fmaxf(o.x, o.y), fmaxf(o.z, o.w)) : -INFINITY;
#pragma unroll
    for (int off = 16; off > 0; off >>= 1)
        m = fmaxf(m, __shfl_xor_sync(0xffffffffu, m, off));
    float s = (lane < 10) ? (expf(o.x - m) + expf(o.y - m) + expf(o.z - m) + expf(o.w - m)) : 0.f;
#pragma unroll
    for (int off = 16; off > 0; off >>= 1)
        s += __shfl_xor_sync(0xffffffffu, s, off);
    float l = m + logf(s);
    if (lane < 10) {
        *(float4*)(out + (size_t)node * 40 + lane * 4) =
            make_float4(o.x - l, o.y - l, o.z - l, o.w - l);
    }
}

// ---------------- batchnorm finalize ----------------
__global__ void k_bnfin(const float* __restrict__ gamma, const float* __restrict__ beta, int n) {
    int c = threadIdx.x;
    float inv_n = 1.0f / (float)n;
    float mu = g_sum[c] * inv_n;
    float var = g_sq[c] * inv_n - mu * mu;
    float rstd = rsqrtf(var + 1e-5f);
    float a = gamma[c] * rstd;
    g_bna[c] = a;
    g_bnb[c] = beta[c] - mu * a;
}

// ---------------- host orchestration ----------------
extern "C" void kernel_launch(void* const* d_in, const int* in_sizes, int n_in,
                              void* d_out, int out_size)
{
    const float* x   = (const float*)d_in[0];
    const int*   ei  = (const int*)d_in[1];
    const float* W0  = (const float*)d_in[2];
    const float* b0  = (const float*)d_in[3];
    const float* W1  = (const float*)d_in[4];
    const float* b1  = (const float*)d_in[5];
    const float* W2  = (const float*)d_in[6];
    const float* b2  = (const float*)d_in[7];
    const float* g0  = (const float*)d_in[8];
    const float* bt0 = (const float*)d_in[9];
    const float* g1  = (const float*)d_in[10];
    const float* bt1 = (const float*)d_in[11];
    float* out = (float*)d_out;

    int N = in_sizes[0] / DH;
    int E = in_sizes[1] / 2;
    const int* src = ei;
    const int* dst = ei + E;

    float *dinv, *h1, *h2, *bna, *bnb;
    int *deg, *rowptr, *cursor, *adj;
    cudaGetSymbolAddress((void**)&dinv, g_dinv);
    cudaGetSymbolAddress((void**)&h1, g_h1);
    cudaGetSymbolAddress((void**)&h2, g_h2);
    cudaGetSymbolAddress((void**)&bna, g_bna);
    cudaGetSymbolAddress((void**)&bnb, g_bnb);
    cudaGetSymbolAddress((void**)&deg, g_deg);
    cudaGetSymbolAddress((void**)&rowptr, g_rowptr);
    cudaGetSymbolAddress((void**)&cursor, g_cursor);
    cudaGetSymbolAddress((void**)&adj, g_adj);

    // ---- CSR build (once) ----
    k_zero_deg<<<(N + 255) / 256, 256>>>(deg, N);
    k_count<<<(E + 255) / 256, 256>>>(dst, deg, E);
    k_scan<<<1, 1024>>>(deg, rowptr, cursor, dinv, N);
    k_fill<<<(E + 255) / 256, 256>>>(src, dst, cursor, adj, E);

    int gemm_blocks = (N + 63) / 64;
    int agg_grid = 1536;                     // grid-stride: ~4 nodes per warp

    // ---- layer 0: conv -> agg (+bn stats) -> bn finalize ----
    gemm128<false><<<gemm_blocks, 256>>>(x, W0, h1, dinv, nullptr, nullptr, N);
    k_agg128<true><<<agg_grid, 256>>>(h1, rowptr, adj, dinv, b0, h2, N);
    k_bnfin<<<1, 128>>>(g0, bt0, N);

    // ---- layer 1: (bn0+relu fused) conv -> agg (+bn stats) -> bn finalize ----
    gemm128<true><<<gemm_blocks, 256>>>(h2, W1, h1, dinv, bna, bnb, N);
    k_agg128<true><<<agg_grid, 256>>>(h1, rowptr, adj, dinv, b1, h2, N);
    k_bnfin<<<1, 128>>>(g1, bt1, N);

    // ---- layer 2: (bn1+relu fused) conv -> agg + fused log_softmax ----
    gemm40<<<gemm_blocks, 256>>>(h2, W2, h1, dinv, bna, bnb, N);
    k_agg40<<<(N + 7) / 8, 256>>>(h1, rowptr, adj, dinv, b2, out, N);
}